// round 10
// baseline (speedup 1.0000x reference)
#include <cuda_runtime.h>
#include <cstddef>

// Shapes fixed by the problem
#define Nn 8
#define Cc 128
#define Tt 32
#define HWp 784                        // 28*28
#define TOTAL ((size_t)Nn*Cc*Tt*HWp)   // 25,690,112 floats
#define N4    (TOTAL/4)                // 6,422,528 float4

#define BLK       256
#define CP_GRID   6272                 // N4 = CP_GRID*BLK*4 exactly
#define COLD_GRID (Nn*Cc)              // 1024 attention tile blocks
#define GRID      (CP_GRID + COLD_GRID)
#define STRD      ((size_t)CP_GRID * BLK)   // 1,605,632

// ---------------------------------------------------------------------------
// ONE kernel, ONE graph node, split grid:
//   blocks [0, 6272):     copy blocks.  alpha==0 -> straight-line 4xfloat4
//                         copy (exact R3 shape: branch decided BEFORE the
//                         loads so ptxas front-batches all 4 LDG.128);
//                         alpha!=0 -> exit (attention blocks own the output).
//   blocks [6272, 7296):  attention blocks.  alpha==0 -> exit; else block
//                         nc = bid-6272 independently computes the full
//                         energy for its n (redundant recompute -> no grid
//                         barrier, no global scratch), softmaxes it, writes
//                         out = x + alpha * attn @ x for its disjoint tile.
// Writers are disjoint for either alpha value -> deterministic, race-free.
//
// smem: single 4224 B buffer overlaid (tile chunk, then attn matrix) to
// minimize per-CTA smem and keep one-shot CTA churn cheap.
// ---------------------------------------------------------------------------
__global__ void __launch_bounds__(BLK, 8) fused_kernel(
        const float* __restrict__ x, const float* __restrict__ alpha,
        float* __restrict__ out) {
    const float a = __ldg(alpha);

    if (blockIdx.x < CP_GRID) {
        if (a != 0.0f) return;         // attention blocks will write out
        const float4* __restrict__ x4 = (const float4*)x;
        float4* __restrict__       o4 = (float4*)out;
        const size_t i = (size_t)blockIdx.x * BLK + threadIdx.x;
        float4 v0 = __ldcs(x4 + i);
        float4 v1 = __ldcs(x4 + i +     STRD);
        float4 v2 = __ldcs(x4 + i + 2 * STRD);
        float4 v3 = __ldcs(x4 + i + 3 * STRD);
        __stcs(o4 + i,            v0);
        __stcs(o4 + i +     STRD, v1);
        __stcs(o4 + i + 2 * STRD, v2);
        __stcs(o4 + i + 3 * STRD, v3);
        return;
    }

    // ================== attention blocks (cold) ==================
    if (a == 0.0f) return;             // copy blocks already wrote out

    const int nc = blockIdx.x - CP_GRID;      // 0..1023
    const int n  = nc >> 7;                   // nc / Cc
    const int tid = threadIdx.x;

    // Overlaid buffer: phase 1 tile chunk tile(t,j)=buf[t*33+j] (pad 33 ->
    // conflict-free); phase 2 attn(t,s)=buf[t*33+s].
    __shared__ float buf[Tt * 33];            // 4224 B

    // Full energy for this n: E[t][s] = sum_c sum_hw x[n,c,t,hw]*x[n,c,s,hw]
    float acc[4] = {0.f, 0.f, 0.f, 0.f};
    for (int c = 0; c < Cc; c++) {
        const float* __restrict__ A =
            x + ((size_t)n * Cc + c) * (Tt * HWp);
        for (int hw0 = 0; hw0 < HWp; hw0 += 32) {
            for (int e = tid; e < Tt * 32; e += BLK) {
                int t = e >> 5, j = e & 31;
                int hw = hw0 + j;
                buf[t * 33 + j] = (hw < HWp) ? A[t * HWp + hw] : 0.0f;
            }
            __syncthreads();
            #pragma unroll
            for (int k = 0; k < 4; k++) {
                int p = tid + k * BLK;         // (t,s) pair 0..1023
                int t = p >> 5, s = p & 31;
                float v = 0.f;
                #pragma unroll
                for (int j = 0; j < 32; j++)
                    v = fmaf(buf[t * 33 + j], buf[s * 33 + j], v);
                acc[k] += v;
            }
            __syncthreads();
        }
    }
    // Tile no longer needed: overlay energy into buf.
    #pragma unroll
    for (int k = 0; k < 4; k++) {
        int p = tid + k * BLK;
        buf[(p >> 5) * 33 + (p & 31)] = acc[k];
    }
    __syncthreads();

    // Row softmax: 8 warps, rows t = w, w+8, w+16, w+24
    {
        const int lane = tid & 31, w = tid >> 5;
        #pragma unroll
        for (int r = 0; r < 4; r++) {
            int t = w + r * 8;
            float v = buf[t * 33 + lane];
            float m = v;
            #pragma unroll
            for (int o = 16; o > 0; o >>= 1)
                m = fmaxf(m, __shfl_xor_sync(0xffffffffu, m, o));
            float p = __expf(v - m);
            float ssum = p;
            #pragma unroll
            for (int o = 16; o > 0; o >>= 1)
                ssum += __shfl_xor_sync(0xffffffffu, ssum, o);
            buf[t * 33 + lane] = p / ssum;
        }
    }
    __syncthreads();

    // Write this block's tile: out = x + a * attn @ x
    {
        const float* __restrict__ A = x   + (size_t)nc * (Tt * HWp);
        float* __restrict__       O = out + (size_t)nc * (Tt * HWp);
        for (int hw = tid; hw < HWp; hw += BLK) {
            #pragma unroll 4
            for (int t = 0; t < Tt; t++) {
                float s_acc = 0.f;
                #pragma unroll
                for (int s = 0; s < Tt; s++)
                    s_acc = fmaf(buf[t * 33 + s], A[s * HWp + hw], s_acc);
                O[t * HWp + hw] = fmaf(a, s_acc, A[t * HWp + hw]);
            }
        }
    }
}

// ---------------------------------------------------------------------------
extern "C" void kernel_launch(void* const* d_in, const int* in_sizes, int n_in,
                              void* d_out, int out_size) {
    const float* x     = (const float*)d_in[0];
    const float* alpha = (const float*)d_in[1];
    if (n_in >= 2 && in_sizes[0] == 1) {   // defensive order swap
        x     = (const float*)d_in[1];
        alpha = (const float*)d_in[0];
    }
    float* out = (float*)d_out;

    fused_kernel<<<GRID, BLK>>>(x, alpha, out);
}